// round 9
// baseline (speedup 1.0000x reference)
#include <cuda_runtime.h>
#include <math.h>

#define D_IN 118
#define MAXB 524288
#define THREADS 256
#define MAXBLK (MAXB/THREADS)

// scratch (static device globals; no allocation)
__device__ float4 g_z4[MAXB];          // per-sample z[4]
__device__ double g_part[MAXBLK*32];   // per-block partial moments (30 used, pad 32)
__device__ double g_S[32];             // final 30 moments
__device__ float  g_params[32];        // mu[8], rowsum[8], coef[2], max_val

#define SMEM_FLOATS 18771
#define SMEM_BYTES (SMEM_FLOATS*4)

__global__ __launch_bounds__(THREADS) void fwd_kernel(
    const float* __restrict__ x,
    const float* __restrict__ eW0, const float* __restrict__ eb0,
    const float* __restrict__ eW1, const float* __restrict__ eb1,
    const float* __restrict__ eW2, const float* __restrict__ eb2,
    const float* __restrict__ eW3, const float* __restrict__ eb3,
    const float* __restrict__ dW0, const float* __restrict__ db0,
    const float* __restrict__ dW1, const float* __restrict__ db1,
    const float* __restrict__ dW2, const float* __restrict__ db2,
    const float* __restrict__ dW3, const float* __restrict__ db3,
    const float* __restrict__ gW0, const float* __restrict__ gb0,
    const float* __restrict__ gW1, const float* __restrict__ gb1,
    float* __restrict__ dec_out, int B)
{
    extern __shared__ float sw[];
    float* sW0  = sw;            // [118][60] input-major (as given)
    float* sW1T = sW0+7080;      // [30][60]  output-major
    float* sW2T = sW1T+1800;     // [10][30]
    float* sW3  = sW2T+300;      // [10]
    float* sD0  = sW3+10;        // [10]
    float* sD1T = sD0+10;        // [30][10]
    float* sD2T = sD1T+300;      // [60][30]
    float* sD3T = sD2T+1800;     // [118][60]
    float* sG0T = sD3T+7080;     // [10][4]
    float* sG1T = sG0T+40;       // [2][10]
    float* sEB0 = sG1T+20;       // 60
    float* sEB1 = sEB0+60;       // 30
    float* sEB2 = sEB1+30;       // 10
    float* sEB3 = sEB2+10;       // 1
    float* sDB0 = sEB3+1;        // 10
    float* sDB1 = sDB0+10;       // 30
    float* sDB2 = sDB1+30;       // 60
    float* sDB3 = sDB2+60;       // 118
    float* sGB0 = sDB3+118;      // 10
    float* sGB1 = sGB0+10;       // 2

    const int tid = threadIdx.x;
    for (int i=tid;i<7080;i+=THREADS) sW0[i]=eW0[i];
    for (int i=tid;i<1800;i+=THREADS){ int j=i/30,k=i%30; sW1T[k*60+j]=eW1[i]; }
    for (int i=tid;i<300;i+=THREADS){ int j=i/10,k=i%10; sW2T[k*30+j]=eW2[i]; }
    for (int i=tid;i<10;i+=THREADS){ sW3[i]=eW3[i]; sD0[i]=dW0[i]; sDB0[i]=db0[i]; sGB0[i]=gb0[i]; sEB2[i]=eb2[i]; }
    for (int i=tid;i<300;i+=THREADS){ int j=i/30,k=i%30; sD1T[k*10+j]=dW1[i]; }
    for (int i=tid;i<1800;i+=THREADS){ int j=i/60,k=i%60; sD2T[k*30+j]=dW2[i]; }
    for (int i=tid;i<7080;i+=THREADS){ int j=i/118,k=i%118; sD3T[k*60+j]=dW3[i]; }
    for (int i=tid;i<40;i+=THREADS){ int g=i/10,j=i%10; sG0T[j*4+g]=gW0[i]; }
    for (int i=tid;i<20;i+=THREADS){ int j=i/2,k=i%2; sG1T[k*10+j]=gW1[i]; }
    for (int i=tid;i<60;i+=THREADS){ sEB0[i]=eb0[i]; sDB2[i]=db2[i]; }
    for (int i=tid;i<30;i+=THREADS){ sEB1[i]=eb1[i]; sDB1[i]=db1[i]; }
    for (int i=tid;i<118;i+=THREADS) sDB3[i]=db3[i];
    if (tid==0) sEB3[0]=eb3[0];
    if (tid<2) sGB1[tid]=gb1[tid];
    __syncthreads();

    const int b = blockIdx.x*THREADS + tid;
    float v[30];
    if (b < B) {
        const float2* x2 = (const float2*)(x + (size_t)b*D_IN);
        // ---------------- encoder L1: 118 -> 60 (relu) ----------------
        float h1[60];
        #pragma unroll
        for (int j=0;j<60;j++) h1[j]=sEB0[j];
        float sx=0.f, sxx=0.f;
        #pragma unroll 1
        for (int i2=0;i2<59;i2++){
            float2 xv = x2[i2];
            sx += xv.x+xv.y; sxx = fmaf(xv.x,xv.x,fmaf(xv.y,xv.y,sxx));
            const float* w0 = sW0 + (2*i2)*60;
            #pragma unroll
            for (int j=0;j<60;j++) h1[j] = fmaf(xv.x, w0[j], h1[j]);
            #pragma unroll
            for (int j=0;j<60;j++) h1[j] = fmaf(xv.y, w0[60+j], h1[j]);
        }
        #pragma unroll
        for (int j=0;j<60;j++) h1[j]=fmaxf(h1[j],0.f);

        // ---------------- encoder L2: 60 -> 30 (relu) ----------------
        float h2l[30];
        #pragma unroll 1
        for (int k=0;k<30;k++){
            const float* w = sW1T + k*60;
            float a0=sEB1[k], a1=0.f;
            #pragma unroll
            for (int j=0;j<60;j+=2){ a0=fmaf(h1[j],w[j],a0); a1=fmaf(h1[j+1],w[j+1],a1); }
            h2l[k]=fmaxf(a0+a1,0.f);
        }
        float h2[30];
        #pragma unroll
        for (int k=0;k<30;k++) h2[k]=h2l[k];

        // ---------------- encoder L3: 30 -> 10 (relu) ----------------
        float h3[10];
        #pragma unroll
        for (int k=0;k<10;k++){
            const float* w=sW2T+k*30;
            float a=sEB2[k];
            #pragma unroll
            for (int j=0;j<30;j++) a=fmaf(h2[j],w[j],a);
            h3[k]=fmaxf(a,0.f);
        }
        // ---------------- encoder L4: 10 -> 1 ----------------
        float enc=sEB3[0];
        #pragma unroll
        for (int j=0;j<10;j++) enc=fmaf(h3[j],sW3[j],enc);

        // ---------------- decoder L1: 1 -> 10 (tanh) ----------------
        float d1[10];
        #pragma unroll
        for (int k=0;k<10;k++) d1[k]=tanhf(fmaf(enc,sD0[k],sDB0[k]));

        // ---------------- decoder L2: 10 -> 30 (tanh) ----------------
        float d2[30];
        #pragma unroll
        for (int k=0;k<30;k++){
            const float* w=sD1T+k*10;
            float a=sDB1[k];
            #pragma unroll
            for (int j=0;j<10;j++) a=fmaf(d1[j],w[j],a);
            d2[k]=tanhf(a);
        }
        // ---------------- decoder L3: 30 -> 60 (tanh) ----------------
        float d3l[60];
        #pragma unroll 1
        for (int k=0;k<60;k++){
            const float* w=sD2T+k*30;
            float a0=sDB2[k],a1=0.f;
            #pragma unroll
            for (int j=0;j<30;j+=2){ a0=fmaf(d2[j],w[j],a0); a1=fmaf(d2[j+1],w[j+1],a1); }
            d3l[k]=tanhf(a0+a1);
        }
        float d3[60];
        #pragma unroll
        for (int k=0;k<60;k++) d3[k]=d3l[k];

        // ---------------- decoder L4: 60 -> 118, stream + stats ----------------
        float xd=0.f, dd=0.f, df=0.f;
        float2* dout2 = (float2*)(dec_out + (size_t)b*D_IN);
        #pragma unroll 1
        for (int k2=0;k2<59;k2++){
            const float* w0=sD3T + (2*k2)*60;
            const float* w1=w0+60;
            float a0=sDB3[2*k2], a0b=0.f, a1=sDB3[2*k2+1], a1b=0.f;
            #pragma unroll
            for (int j=0;j<60;j+=2){ a0=fmaf(d3[j],w0[j],a0); a0b=fmaf(d3[j+1],w0[j+1],a0b); }
            #pragma unroll
            for (int j=0;j<60;j+=2){ a1=fmaf(d3[j],w1[j],a1); a1b=fmaf(d3[j+1],w1[j+1],a1b); }
            float o0=a0+a0b, o1=a1+a1b;
            float2 xv=x2[k2];
            xd = fmaf(xv.x,o0,fmaf(xv.y,o1,xd));
            dd = fmaf(o0,o0,fmaf(o1,o1,dd));
            float t0=xv.x-o0, t1=xv.y-o1;
            df = fmaf(t0,t0,fmaf(t1,t1,df));
            dout2[k2]=make_float2(o0,o1);
        }

        // ---------------- features z ----------------
        float xn=sqrtf(sxx), dn=sqrtf(dd);
        float rel = sqrtf(df)/fmaxf(xn,1e-10f);
        float cs  = xd/fmaxf(xn*dn,1e-10f);
        float mean = sx*(1.f/118.f);
        float var = sxx*(1.f/118.f) - mean*mean;
        float stdv = sqrtf(fmaxf(var,0.f));
        float zz[4]={enc,rel,cs,stdv};
        g_z4[b]=make_float4(enc,rel,cs,stdv);

        // ---------------- estimation net + softmax ----------------
        float l0=sGB1[0], l1=sGB1[1];
        #pragma unroll
        for (int j=0;j<10;j++){
            float a=sGB0[j];
            #pragma unroll
            for (int g=0;g<4;g++) a=fmaf(zz[g],sG0T[j*4+g],a);
            float th=tanhf(a);
            l0=fmaf(th,sG1T[j],l0);
            l1=fmaf(th,sG1T[10+j],l1);
        }
        float m=fmaxf(l0,l1);
        float e0=expf(l0-m), e1=expf(l1-m);
        float is=1.f/(e0+e1);
        float g0=e0*is, g1=e1*is;

        // 30 moments: per comp k: [gamma, gamma*z(4), gamma*z_a*z_b (10 sym)]
        v[0]=g0;
        v[1]=g0*zz[0]; v[2]=g0*zz[1]; v[3]=g0*zz[2]; v[4]=g0*zz[3];
        v[5]=v[1]*zz[0]; v[6]=v[1]*zz[1]; v[7]=v[1]*zz[2]; v[8]=v[1]*zz[3];
        v[9]=v[2]*zz[1]; v[10]=v[2]*zz[2]; v[11]=v[2]*zz[3];
        v[12]=v[3]*zz[2]; v[13]=v[3]*zz[3];
        v[14]=v[4]*zz[3];
        v[15]=g1;
        v[16]=g1*zz[0]; v[17]=g1*zz[1]; v[18]=g1*zz[2]; v[19]=g1*zz[3];
        v[20]=v[16]*zz[0]; v[21]=v[16]*zz[1]; v[22]=v[16]*zz[2]; v[23]=v[16]*zz[3];
        v[24]=v[17]*zz[1]; v[25]=v[17]*zz[2]; v[26]=v[17]*zz[3];
        v[27]=v[18]*zz[2]; v[28]=v[18]*zz[3];
        v[29]=v[19]*zz[3];
    } else {
        #pragma unroll
        for (int c=0;c<30;c++) v[c]=0.f;
    }

    // ---------------- deterministic block reduction ----------------
    __shared__ float sred[8*30];
    const unsigned lane = tid&31u, w = (unsigned)tid>>5;
    #pragma unroll
    for (int c=0;c<30;c++){
        float r=v[c];
        #pragma unroll
        for (int o=16;o;o>>=1) r += __shfl_down_sync(0xffffffffu,r,o);
        if (lane==0) sred[w*30+c]=r;
    }
    __syncthreads();
    if (tid<30){
        double s=0.0;
        #pragma unroll
        for (int ww=0;ww<8;ww++) s += (double)sred[ww*30+tid];
        g_part[(size_t)blockIdx.x*32+tid]=s;
    }
}

// ---------------- stage 1: reduce block partials to 30 global moments ----------------
__global__ __launch_bounds__(1024) void reduce30_kernel(int nblk)
{
    __shared__ double S[32];
    int w=threadIdx.x>>5, lane=threadIdx.x&31;
    if (w<30){
        double s=0.0;
        for (int bl=lane; bl<nblk; bl+=32) s+=g_part[(size_t)bl*32+w];
        #pragma unroll
        for (int o=16;o;o>>=1) s += __shfl_down_sync(0xffffffffu,s,o);
        if (lane==0) S[w]=s;
    }
    __syncthreads();
    if (threadIdx.x<30) g_S[threadIdx.x]=S[threadIdx.x];
}

// ---------------- stage 2: GMM params, inverse, det, max_val, cov_diag (1 warp) ----------------
__global__ __launch_bounds__(32) void params_kernel(float* __restrict__ covdiag_out, int Bn)
{
    if (threadIdx.x!=0) return;
    const double TWO_PI=6.283185307179586;
    const double tp4=TWO_PI*TWO_PI*TWO_PI*TWO_PI;
    const int map[4][4]={{0,1,2,3},{1,4,5,6},{2,5,7,8},{3,6,8,9}};
    float4 zf=g_z4[0];
    double z0[4]={(double)zf.x,(double)zf.y,(double)zf.z,(double)zf.w};
    double covdiag=0.0;
    double ett0[2], coef[2], muv[2][4], rs[2][4];
    for (int k=0;k<2;k++){
        const double* Sk=g_S+k*15;
        double sg=Sk[0];
        double phi=sg/(double)Bn;
        double mu[4];
        for (int g=0;g<4;g++) mu[g]=Sk[1+g]/sg;
        double a[4][4], inv[4][4];
        for (int g=0;g<4;g++) for (int h=0;h<4;h++){
            a[g][h]=Sk[5+map[g][h]]/sg - mu[g]*mu[h];
            inv[g][h]=(g==h)?1.0:0.0;
        }
        for (int g=0;g<4;g++) a[g][g]+=1e-12;
        for (int g=0;g<4;g++) covdiag += 1.0/a[g][g];
        double det=1.0;
        for (int c=0;c<4;c++){
            int p=c;
            for (int r=c+1;r<4;r++) if (fabs(a[r][c])>fabs(a[p][c])) p=r;
            if (p!=c){
                for (int j=0;j<4;j++){ double t=a[c][j];a[c][j]=a[p][j];a[p][j]=t;
                                       t=inv[c][j];inv[c][j]=inv[p][j];inv[p][j]=t; }
                det=-det;
            }
            double piv=a[c][c]; det*=piv; double ip=1.0/piv;
            for (int j=0;j<4;j++){ a[c][j]*=ip; inv[c][j]*=ip; }
            for (int r=0;r<4;r++) if (r!=c){
                double f=a[r][c];
                for (int j=0;j<4;j++){ a[r][j]-=f*a[c][j]; inv[r][j]-=f*inv[c][j]; }
            }
        }
        double detcov=det*tp4;
        for (int g=0;g<4;g++){
            double r=0.0; for (int h=0;h<4;h++) r+=inv[g][h];
            rs[k][g]=r; muv[k][g]=mu[g];
        }
        coef[k]=phi/(sqrt(detcov)+1e-12);
        double ss=0.0, in_=0.0;
        for (int g=0;g<4;g++){ double zm=z0[g]-mu[g]; ss+=zm; in_+=zm*rs[k][g]; }
        ett0[k]=-0.5*in_*ss;
    }
    double maxv=fmax(fmax(ett0[0],ett0[1]),0.0);
    for (int k=0;k<2;k++){
        for (int g=0;g<4;g++){ g_params[k*4+g]=(float)muv[k][g]; g_params[8+k*4+g]=(float)rs[k][g]; }
        g_params[16+k]=(float)coef[k];
    }
    g_params[18]=(float)maxv;
    covdiag_out[0]=(float)covdiag;
}

// ---------------- per-sample energy ----------------
__global__ __launch_bounds__(256) void energy_kernel(float* __restrict__ eout, int Bn)
{
    int b=blockIdx.x*blockDim.x+threadIdx.x;
    if (b>=Bn) return;
    float4 zv=g_z4[b];
    float z[4]={zv.x,zv.y,zv.z,zv.w};
    float mv=g_params[18];
    float acc=0.f;
    #pragma unroll
    for (int k=0;k<2;k++){
        float ss=0.f, in_=0.f;
        #pragma unroll
        for (int g=0;g<4;g++){
            float zm=z[g]-g_params[k*4+g];
            ss+=zm;
            in_=fmaf(zm,g_params[8+k*4+g],in_);
        }
        float e=-0.5f*in_*ss - mv;
        e=fminf(fmaxf(e,-50.f),50.f);
        acc = fmaf(g_params[16+k], expf(e), acc);
    }
    eout[b]=-mv - logf(acc+1e-12f);
}

extern "C" void kernel_launch(void* const* d_in, const int* in_sizes, int n_in,
                              void* d_out, int out_size)
{
    (void)n_in; (void)out_size;
    const float* x   = (const float*)d_in[0];
    const float* eW0 = (const float*)d_in[1];
    const float* eb0 = (const float*)d_in[2];
    const float* eW1 = (const float*)d_in[3];
    const float* eb1 = (const float*)d_in[4];
    const float* eW2 = (const float*)d_in[5];
    const float* eb2 = (const float*)d_in[6];
    const float* eW3 = (const float*)d_in[7];
    const float* eb3 = (const float*)d_in[8];
    const float* dW0 = (const float*)d_in[9];
    const float* db0 = (const float*)d_in[10];
    const float* dW1 = (const float*)d_in[11];
    const float* db1 = (const float*)d_in[12];
    const float* dW2 = (const float*)d_in[13];
    const float* db2 = (const float*)d_in[14];
    const float* dW3 = (const float*)d_in[15];
    const float* db3 = (const float*)d_in[16];
    const float* gW0 = (const float*)d_in[17];
    const float* gb0 = (const float*)d_in[18];
    const float* gW1 = (const float*)d_in[19];
    const float* gb1 = (const float*)d_in[20];

    int B = in_sizes[0]/D_IN;
    float* out = (float*)d_out;
    float* dec_out = out;                       // [B,118]
    float* e_out   = out + (size_t)B*D_IN;      // [B]
    float* cd_out  = e_out + B;                 // scalar

    int nblk = (B + THREADS - 1)/THREADS;

    cudaFuncSetAttribute(fwd_kernel, cudaFuncAttributeMaxDynamicSharedMemorySize, SMEM_BYTES);

    fwd_kernel<<<nblk, THREADS, SMEM_BYTES>>>(
        x, eW0,eb0,eW1,eb1,eW2,eb2,eW3,eb3,
        dW0,db0,dW1,db1,dW2,db2,dW3,db3,
        gW0,gb0,gW1,gb1, dec_out, B);
    reduce30_kernel<<<1, 1024>>>(nblk);
    params_kernel<<<1, 32>>>(cd_out, B);
    energy_kernel<<<nblk, THREADS>>>(e_out, B);
}

// round 12
// speedup vs baseline: 1.0690x; 1.0690x over previous
#include <cuda_runtime.h>
#include <math.h>

#define D_IN 118
#define MAXB 524288
#define THREADS 256
#define MAXBLK (MAXB/THREADS)

typedef unsigned long long ull;

__device__ __forceinline__ ull pack2(float lo, float hi){
    ull r; asm("mov.b64 %0, {%1, %2};" : "=l"(r) : "f"(lo), "f"(hi)); return r;
}
__device__ __forceinline__ float2 unpack2(ull v){
    float2 r; asm("mov.b64 {%0, %1}, %2;" : "=f"(r.x), "=f"(r.y) : "l"(v)); return r;
}
__device__ __forceinline__ ull fma2(ull a, ull b, ull c){
    ull d; asm("fma.rn.f32x2 %0, %1, %2, %3;" : "=l"(d) : "l"(a), "l"(b), "l"(c)); return d;
}

// scratch (static device globals; no allocation)
__device__ float4 g_z4[MAXB];          // per-sample z[4]
__device__ double g_part[MAXBLK*32];   // per-block partial moments (30 used, pad 32)
__device__ double g_S[32];             // final 30 moments
__device__ float  g_params[32];        // mu[8], rowsum[8], coef[2], max_val

#define SMEM_FLOATS 18771
#define SMEM_BYTES (SMEM_FLOATS*4)

__global__ __launch_bounds__(THREADS) void fwd_kernel(
    const float* __restrict__ x,
    const float* __restrict__ eW0, const float* __restrict__ eb0,
    const float* __restrict__ eW1, const float* __restrict__ eb1,
    const float* __restrict__ eW2, const float* __restrict__ eb2,
    const float* __restrict__ eW3, const float* __restrict__ eb3,
    const float* __restrict__ dW0, const float* __restrict__ db0,
    const float* __restrict__ dW1, const float* __restrict__ db1,
    const float* __restrict__ dW2, const float* __restrict__ db2,
    const float* __restrict__ dW3, const float* __restrict__ db3,
    const float* __restrict__ gW0, const float* __restrict__ gb0,
    const float* __restrict__ gW1, const float* __restrict__ gb1,
    float* __restrict__ dec_out, int B)
{
    extern __shared__ float sw[];
    float* sW0  = sw;            // [118][60] input-major (as given)
    float* sW1T = sW0+7080;      // [30][60]  output-major
    float* sW2T = sW1T+1800;     // [10][30]
    float* sW3  = sW2T+300;      // [10]  (padded to even base)
    float* sD0  = sW3+10;        // [10]
    float* sD1T = sD0+10;        // [30][10]
    float* sD2T = sD1T+300;      // [60][30]
    float* sD3T = sD2T+1800;     // [118][60]
    float* sG0T = sD3T+7080;     // [10][4]
    float* sG1T = sG0T+40;       // [2][10]
    float* sEB0 = sG1T+20;       // 60
    float* sEB1 = sEB0+60;       // 30
    float* sEB2 = sEB1+30;       // 10
    float* sEB3 = sEB2+10;       // 1
    float* sDB0 = sEB3+1;        // 10
    float* sDB1 = sDB0+10;       // 30
    float* sDB2 = sDB1+30;       // 60
    float* sDB3 = sDB2+60;       // 118
    float* sGB0 = sDB3+118;      // 10
    float* sGB1 = sGB0+10;       // 2

    const int tid = threadIdx.x;
    for (int i=tid;i<7080;i+=THREADS) sW0[i]=eW0[i];
    for (int i=tid;i<1800;i+=THREADS){ int j=i/30,k=i%30; sW1T[k*60+j]=eW1[i]; }
    for (int i=tid;i<300;i+=THREADS){ int j=i/10,k=i%10; sW2T[k*30+j]=eW2[i]; }
    for (int i=tid;i<10;i+=THREADS){ sW3[i]=eW3[i]; sD0[i]=dW0[i]; sDB0[i]=db0[i]; sGB0[i]=gb0[i]; sEB2[i]=eb2[i]; }
    for (int i=tid;i<300;i+=THREADS){ int j=i/30,k=i%30; sD1T[k*10+j]=dW1[i]; }
    for (int i=tid;i<1800;i+=THREADS){ int j=i/60,k=i%60; sD2T[k*30+j]=dW2[i]; }
    for (int i=tid;i<7080;i+=THREADS){ int j=i/118,k=i%118; sD3T[k*60+j]=dW3[i]; }
    for (int i=tid;i<40;i+=THREADS){ int g=i/10,j=i%10; sG0T[j*4+g]=gW0[i]; }
    for (int i=tid;i<20;i+=THREADS){ int j=i/2,k=i%2; sG1T[k*10+j]=gW1[i]; }
    for (int i=tid;i<60;i+=THREADS){ sEB0[i]=eb0[i]; sDB2[i]=db2[i]; }
    for (int i=tid;i<30;i+=THREADS){ sEB1[i]=eb1[i]; sDB1[i]=db1[i]; }
    for (int i=tid;i<118;i+=THREADS) sDB3[i]=db3[i];
    if (tid==0) sEB3[0]=eb3[0];
    if (tid<2) sGB1[tid]=gb1[tid];
    __syncthreads();

    const int b = blockIdx.x*THREADS + tid;
    float v[30];
    if (b < B) {
        const float2* x2 = (const float2*)(x + (size_t)b*D_IN);
        // ---------------- encoder L1: 118 -> 60 (relu), packed over outputs ----------------
        ull h1p[30];
        {
            const ull* bp = (const ull*)sEB0;
            #pragma unroll
            for (int jj=0;jj<30;jj++) h1p[jj]=bp[jj];
        }
        float sx=0.f, sxx=0.f;
        #pragma unroll 1
        for (int i2=0;i2<59;i2++){
            float2 xv = x2[i2];
            sx += xv.x+xv.y; sxx = fmaf(xv.x,xv.x,fmaf(xv.y,xv.y,sxx));
            ull xx = pack2(xv.x,xv.x);
            ull xy = pack2(xv.y,xv.y);
            const ull* w0p = (const ull*)(sW0 + (2*i2)*60);
            const ull* w1p = w0p + 30;
            #pragma unroll
            for (int jj=0;jj<30;jj++) h1p[jj] = fma2(xx, w0p[jj], h1p[jj]);
            #pragma unroll
            for (int jj=0;jj<30;jj++) h1p[jj] = fma2(xy, w1p[jj], h1p[jj]);
        }
        #pragma unroll
        for (int jj=0;jj<30;jj++){
            float2 p=unpack2(h1p[jj]);
            h1p[jj]=pack2(fmaxf(p.x,0.f),fmaxf(p.y,0.f));
        }

        // ---------------- encoder L2: 60 -> 30 (relu), even/odd pair reduction ----------------
        float h2[30];
        #pragma unroll 1
        for (int k=0;k<30;k++){
            const ull* wp = (const ull*)(sW1T + k*60);
            ull acc = pack2(sEB1[k], 0.f);
            #pragma unroll
            for (int jj=0;jj<30;jj++) acc = fma2(h1p[jj], wp[jj], acc);
            float2 p=unpack2(acc);
            h2[k]=fmaxf(p.x+p.y,0.f);
        }
        ull h2p[15];
        #pragma unroll
        for (int jj=0;jj<15;jj++) h2p[jj]=pack2(h2[2*jj],h2[2*jj+1]);

        // ---------------- encoder L3: 30 -> 10 (relu) ----------------
        float h3[10];
        #pragma unroll
        for (int k=0;k<10;k++){
            const ull* wp=(const ull*)(sW2T+k*30);
            ull acc = pack2(sEB2[k], 0.f);
            #pragma unroll
            for (int jj=0;jj<15;jj++) acc = fma2(h2p[jj], wp[jj], acc);
            float2 p=unpack2(acc);
            h3[k]=fmaxf(p.x+p.y,0.f);
        }
        ull h3p[5];
        #pragma unroll
        for (int jj=0;jj<5;jj++) h3p[jj]=pack2(h3[2*jj],h3[2*jj+1]);

        // ---------------- encoder L4: 10 -> 1 ----------------
        float enc;
        {
            const ull* wp=(const ull*)sW3;
            ull acc = pack2(sEB3[0], 0.f);
            #pragma unroll
            for (int jj=0;jj<5;jj++) acc = fma2(h3p[jj], wp[jj], acc);
            float2 p=unpack2(acc);
            enc=p.x+p.y;
        }

        // ---------------- decoder L1: 1 -> 10 (tanh) ----------------
        float d1[10];
        #pragma unroll
        for (int k=0;k<10;k++) d1[k]=tanhf(fmaf(enc,sD0[k],sDB0[k]));
        ull d1p[5];
        #pragma unroll
        for (int jj=0;jj<5;jj++) d1p[jj]=pack2(d1[2*jj],d1[2*jj+1]);

        // ---------------- decoder L2: 10 -> 30 (tanh) ----------------
        float d2[30];
        #pragma unroll
        for (int k=0;k<30;k++){
            const ull* wp=(const ull*)(sD1T+k*10);
            ull acc = pack2(sDB1[k], 0.f);
            #pragma unroll
            for (int jj=0;jj<5;jj++) acc = fma2(d1p[jj], wp[jj], acc);
            float2 p=unpack2(acc);
            d2[k]=tanhf(p.x+p.y);
        }
        ull d2p[15];
        #pragma unroll
        for (int jj=0;jj<15;jj++) d2p[jj]=pack2(d2[2*jj],d2[2*jj+1]);

        // ---------------- decoder L3: 30 -> 60 (tanh) ----------------
        float d3[60];
        #pragma unroll 1
        for (int k=0;k<60;k++){
            const ull* wp=(const ull*)(sD2T+k*30);
            ull acc = pack2(sDB2[k], 0.f);
            #pragma unroll
            for (int jj=0;jj<15;jj++) acc = fma2(d2p[jj], wp[jj], acc);
            float2 p=unpack2(acc);
            d3[k]=tanhf(p.x+p.y);
        }
        ull d3p[30];
        #pragma unroll
        for (int jj=0;jj<30;jj++) d3p[jj]=pack2(d3[2*jj],d3[2*jj+1]);

        // ---------------- decoder L4: 60 -> 118, stream + stats ----------------
        float xd=0.f, dd=0.f, df=0.f;
        float2* dout2 = (float2*)(dec_out + (size_t)b*D_IN);
        #pragma unroll 1
        for (int k2=0;k2<59;k2++){
            const ull* w0p=(const ull*)(sD3T + (2*k2)*60);
            const ull* w1p=w0p+30;
            ull acc0 = pack2(sDB3[2*k2], 0.f);
            ull acc1 = pack2(sDB3[2*k2+1], 0.f);
            #pragma unroll
            for (int jj=0;jj<30;jj++) acc0 = fma2(d3p[jj], w0p[jj], acc0);
            #pragma unroll
            for (int jj=0;jj<30;jj++) acc1 = fma2(d3p[jj], w1p[jj], acc1);
            float2 p0=unpack2(acc0), p1=unpack2(acc1);
            float o0=p0.x+p0.y, o1=p1.x+p1.y;
            float2 xv=x2[k2];
            xd = fmaf(xv.x,o0,fmaf(xv.y,o1,xd));
            dd = fmaf(o0,o0,fmaf(o1,o1,dd));
            float t0=xv.x-o0, t1=xv.y-o1;
            df = fmaf(t0,t0,fmaf(t1,t1,df));
            dout2[k2]=make_float2(o0,o1);
        }

        // ---------------- features z ----------------
        float xn=sqrtf(sxx), dn=sqrtf(dd);
        float rel = sqrtf(df)/fmaxf(xn,1e-10f);
        float cs  = xd/fmaxf(xn*dn,1e-10f);
        float mean = sx*(1.f/118.f);
        float var = sxx*(1.f/118.f) - mean*mean;
        float stdv = sqrtf(fmaxf(var,0.f));
        float zz[4]={enc,rel,cs,stdv};
        g_z4[b]=make_float4(enc,rel,cs,stdv);

        // ---------------- estimation net + softmax ----------------
        float l0=sGB1[0], l1=sGB1[1];
        #pragma unroll
        for (int j=0;j<10;j++){
            float a=sGB0[j];
            #pragma unroll
            for (int g=0;g<4;g++) a=fmaf(zz[g],sG0T[j*4+g],a);
            float th=tanhf(a);
            l0=fmaf(th,sG1T[j],l0);
            l1=fmaf(th,sG1T[10+j],l1);
        }
        float m=fmaxf(l0,l1);
        float e0=expf(l0-m), e1=expf(l1-m);
        float is=1.f/(e0+e1);
        float g0=e0*is, g1=e1*is;

        // 30 moments: per comp k: [gamma, gamma*z(4), gamma*z_a*z_b (10 sym)]
        v[0]=g0;
        v[1]=g0*zz[0]; v[2]=g0*zz[1]; v[3]=g0*zz[2]; v[4]=g0*zz[3];
        v[5]=v[1]*zz[0]; v[6]=v[1]*zz[1]; v[7]=v[1]*zz[2]; v[8]=v[1]*zz[3];
        v[9]=v[2]*zz[1]; v[10]=v[2]*zz[2]; v[11]=v[2]*zz[3];
        v[12]=v[3]*zz[2]; v[13]=v[3]*zz[3];
        v[14]=v[4]*zz[3];
        v[15]=g1;
        v[16]=g1*zz[0]; v[17]=g1*zz[1]; v[18]=g1*zz[2]; v[19]=g1*zz[3];
        v[20]=v[16]*zz[0]; v[21]=v[16]*zz[1]; v[22]=v[16]*zz[2]; v[23]=v[16]*zz[3];
        v[24]=v[17]*zz[1]; v[25]=v[17]*zz[2]; v[26]=v[17]*zz[3];
        v[27]=v[18]*zz[2]; v[28]=v[18]*zz[3];
        v[29]=v[19]*zz[3];
    } else {
        #pragma unroll
        for (int c=0;c<30;c++) v[c]=0.f;
    }

    // ---------------- deterministic block reduction ----------------
    __shared__ float sred[8*30];
    const unsigned lane = tid&31u, w = (unsigned)tid>>5;
    #pragma unroll
    for (int c=0;c<30;c++){
        float r=v[c];
        #pragma unroll
        for (int o=16;o;o>>=1) r += __shfl_down_sync(0xffffffffu,r,o);
        if (lane==0) sred[w*30+c]=r;
    }
    __syncthreads();
    if (tid<30){
        double s=0.0;
        #pragma unroll
        for (int ww=0;ww<8;ww++) s += (double)sred[ww*30+tid];
        g_part[(size_t)blockIdx.x*32+tid]=s;
    }
}

// ---------------- stage 1: reduce block partials to 30 global moments ----------------
__global__ __launch_bounds__(1024) void reduce30_kernel(int nblk)
{
    __shared__ double S[32];
    int w=threadIdx.x>>5, lane=threadIdx.x&31;
    if (w<30){
        double s=0.0;
        for (int bl=lane; bl<nblk; bl+=32) s+=g_part[(size_t)bl*32+w];
        #pragma unroll
        for (int o=16;o;o>>=1) s += __shfl_down_sync(0xffffffffu,s,o);
        if (lane==0) S[w]=s;
    }
    __syncthreads();
    if (threadIdx.x<30) g_S[threadIdx.x]=S[threadIdx.x];
}

// ---------------- stage 2: GMM params, inverse, det, max_val, cov_diag (1 warp) ----------------
__global__ __launch_bounds__(32) void params_kernel(float* __restrict__ covdiag_out, int Bn)
{
    if (threadIdx.x!=0) return;
    const double TWO_PI=6.283185307179586;
    const double tp4=TWO_PI*TWO_PI*TWO_PI*TWO_PI;
    const int map[4][4]={{0,1,2,3},{1,4,5,6},{2,5,7,8},{3,6,8,9}};
    float4 zf=g_z4[0];
    double z0[4]={(double)zf.x,(double)zf.y,(double)zf.z,(double)zf.w};
    double covdiag=0.0;
    double ett0[2], coef[2], muv[2][4], rs[2][4];
    for (int k=0;k<2;k++){
        const double* Sk=g_S+k*15;
        double sg=Sk[0];
        double phi=sg/(double)Bn;
        double mu[4];
        for (int g=0;g<4;g++) mu[g]=Sk[1+g]/sg;
        double a[4][4], inv[4][4];
        for (int g=0;g<4;g++) for (int h=0;h<4;h++){
            a[g][h]=Sk[5+map[g][h]]/sg - mu[g]*mu[h];
            inv[g][h]=(g==h)?1.0:0.0;
        }
        for (int g=0;g<4;g++) a[g][g]+=1e-12;
        for (int g=0;g<4;g++) covdiag += 1.0/a[g][g];
        double det=1.0;
        for (int c=0;c<4;c++){
            int p=c;
            for (int r=c+1;r<4;r++) if (fabs(a[r][c])>fabs(a[p][c])) p=r;
            if (p!=c){
                for (int j=0;j<4;j++){ double t=a[c][j];a[c][j]=a[p][j];a[p][j]=t;
                                       t=inv[c][j];inv[c][j]=inv[p][j];inv[p][j]=t; }
                det=-det;
            }
            double piv=a[c][c]; det*=piv; double ip=1.0/piv;
            for (int j=0;j<4;j++){ a[c][j]*=ip; inv[c][j]*=ip; }
            for (int r=0;r<4;r++) if (r!=c){
                double f=a[r][c];
                for (int j=0;j<4;j++){ a[r][j]-=f*a[c][j]; inv[r][j]-=f*inv[c][j]; }
            }
        }
        double detcov=det*tp4;
        for (int g=0;g<4;g++){
            double r=0.0; for (int h=0;h<4;h++) r+=inv[g][h];
            rs[k][g]=r; muv[k][g]=mu[g];
        }
        coef[k]=phi/(sqrt(detcov)+1e-12);
        double ss=0.0, in_=0.0;
        for (int g=0;g<4;g++){ double zm=z0[g]-mu[g]; ss+=zm; in_+=zm*rs[k][g]; }
        ett0[k]=-0.5*in_*ss;
    }
    double maxv=fmax(fmax(ett0[0],ett0[1]),0.0);
    for (int k=0;k<2;k++){
        for (int g=0;g<4;g++){ g_params[k*4+g]=(float)muv[k][g]; g_params[8+k*4+g]=(float)rs[k][g]; }
        g_params[16+k]=(float)coef[k];
    }
    g_params[18]=(float)maxv;
    covdiag_out[0]=(float)covdiag;
}

// ---------------- per-sample energy ----------------
__global__ __launch_bounds__(256) void energy_kernel(float* __restrict__ eout, int Bn)
{
    int b=blockIdx.x*blockDim.x+threadIdx.x;
    if (b>=Bn) return;
    float4 zv=g_z4[b];
    float z[4]={zv.x,zv.y,zv.z,zv.w};
    float mv=g_params[18];
    float acc=0.f;
    #pragma unroll
    for (int k=0;k<2;k++){
        float ss=0.f, in_=0.f;
        #pragma unroll
        for (int g=0;g<4;g++){
            float zm=z[g]-g_params[k*4+g];
            ss+=zm;
            in_=fmaf(zm,g_params[8+k*4+g],in_);
        }
        float e=-0.5f*in_*ss - mv;
        e=fminf(fmaxf(e,-50.f),50.f);
        acc = fmaf(g_params[16+k], expf(e), acc);
    }
    eout[b]=-mv - logf(acc+1e-12f);
}

extern "C" void kernel_launch(void* const* d_in, const int* in_sizes, int n_in,
                              void* d_out, int out_size)
{
    (void)n_in; (void)out_size;
    const float* x   = (const float*)d_in[0];
    const float* eW0 = (const float*)d_in[1];
    const float* eb0 = (const float*)d_in[2];
    const float* eW1 = (const float*)d_in[3];
    const float* eb1 = (const float*)d_in[4];
    const float* eW2 = (const float*)d_in[5];
    const float* eb2 = (const float*)d_in[6];
    const float* eW3 = (const float*)d_in[7];
    const float* eb3 = (const float*)d_in[8];
    const float* dW0 = (const float*)d_in[9];
    const float* db0 = (const float*)d_in[10];
    const float* dW1 = (const float*)d_in[11];
    const float* db1 = (const float*)d_in[12];
    const float* dW2 = (const float*)d_in[13];
    const float* db2 = (const float*)d_in[14];
    const float* dW3 = (const float*)d_in[15];
    const float* db3 = (const float*)d_in[16];
    const float* gW0 = (const float*)d_in[17];
    const float* gb0 = (const float*)d_in[18];
    const float* gW1 = (const float*)d_in[19];
    const float* gb1 = (const float*)d_in[20];

    int B = in_sizes[0]/D_IN;
    float* out = (float*)d_out;
    float* dec_out = out;                       // [B,118]
    float* e_out   = out + (size_t)B*D_IN;      // [B]
    float* cd_out  = e_out + B;                 // scalar

    int nblk = (B + THREADS - 1)/THREADS;

    cudaFuncSetAttribute(fwd_kernel, cudaFuncAttributeMaxDynamicSharedMemorySize, SMEM_BYTES);

    fwd_kernel<<<nblk, THREADS, SMEM_BYTES>>>(
        x, eW0,eb0,eW1,eb1,eW2,eb2,eW3,eb3,
        dW0,db0,dW1,db1,dW2,db2,dW3,db3,
        gW0,gb0,gW1,gb1, dec_out, B);
    reduce30_kernel<<<1, 1024>>>(nblk);
    params_kernel<<<1, 32>>>(cd_out, B);
    energy_kernel<<<nblk, THREADS>>>(e_out, B);
}